// round 3
// baseline (speedup 1.0000x reference)
#include <cuda_runtime.h>
#include <math.h>

// ---------------------------------------------------------------------------
// DCTModel: fused upsample(112->896 bilinear) + RGB->YCbCr + 8x8 DCT + channel
// selection, algebraically collapsed.
//
// Key identity: each 8x8 output block depends on only a 3x3 input patch
// (upsample scale ~8x, so the 8 interpolation positions of one block span
// <1 input index -> <=3 consecutive input rows/cols). All additive constants
// (0.5 offset, *255 shift, YCbCr shift, -128) only affect the DC coefficient,
// which is a dropped SUB channel. So:
//
//   out[b, c'*54+m(u,v), i, j]
//     = sum_{r,s<3} W[i][u][r] * W[j][v][s] * t[b,c',base_i+r,base_j+s]
//   t[b,c'] = 127.5 * sum_c RGB2YCBCR[c',c] * x[b,c]
//   W[i][u][r] = (alpha_u/2) * sum_{x<8} cos((2x+1)u pi/16) * Ah[8i+x, base_i+r]
//
// Compute ~0.27 GFMA (trivial). Output = 130 MB of stores -> DRAM-store-bound,
// floor ~20us on B200.
// ---------------------------------------------------------------------------

#define HW 112            // input H == W
#define NPLANE 12544      // 112*112
#define NBATCH 16

__device__ float g_W[HW][8][3];   // fused DCT x upsample weights (rows == cols table)
__device__ int   g_base[HW];      // base input index per block index

__constant__ float c_M[3][3] = {
    { 0.299f,     0.587f,    0.114f   },
    {-0.168736f, -0.331264f, 0.5f     },
    { 0.5f,      -0.418688f, -0.081312f}
};

// Skip mask: SUB_CHANNELS = {0,1,2,3,4,5,8,9,16,24}
#define SUB_MASK 0x000000000101033FULL

// ---------------------------------------------------------------------------
// Init kernel: builds W table in fp64, exactly mirroring numpy's float64
// src/floor/clamp computation. Deterministic; launched on every call.
// ---------------------------------------------------------------------------
__global__ void init_weights_kernel() {
    int i = threadIdx.x;
    if (i >= HW) return;

    int    i0[8];
    double w[8];
    int base = 1 << 30;
    #pragma unroll
    for (int x = 0; x < 8; x++) {
        int o = 8 * i + x;
        double src = ((double)o * 111.0) / 895.0;   // (L-1)/(Lo-1) as numpy does
        int f = (int)floor(src);
        if (f > HW - 2) f = HW - 2;                 // clamp to L-2
        i0[x] = f;
        w[x]  = src - (double)f;
        if (f < base) base = f;
    }
    g_base[i] = base;

    // Per-output-row upsample weights folded onto 3 offsets
    double a[8][3];
    #pragma unroll
    for (int x = 0; x < 8; x++) { a[x][0] = 0.0; a[x][1] = 0.0; a[x][2] = 0.0; }
    #pragma unroll
    for (int x = 0; x < 8; x++) {
        int off = i0[x] - base;          // 0 or 1
        a[x][off]     += 1.0 - w[x];
        a[x][off + 1] += w[x];
    }

    const double PI = 3.14159265358979323846;
    #pragma unroll
    for (int u = 0; u < 8; u++) {
        double alpha = (u == 0) ? (1.0 / sqrt(2.0)) : 1.0;
        #pragma unroll
        for (int r = 0; r < 3; r++) {
            double s = 0.0;
            #pragma unroll
            for (int x = 0; x < 8; x++)
                s += cos(((2 * x + 1) * u) * PI / 16.0) * a[x][r];
            g_W[i][u][r] = (float)(s * alpha * 0.5);   // alpha_u / 2 (nscale split)
        }
    }
}

// ---------------------------------------------------------------------------
// Main kernel: one thread per (b, c', i, j). j = threadIdx.x for coalesced
// stores across the 54 m-planes.
// ---------------------------------------------------------------------------
__global__ __launch_bounds__(448)
void dct_main_kernel(const float* __restrict__ x, float* __restrict__ out) {
    const int j  = threadIdx.x;                          // 0..111
    const int i  = blockIdx.x * blockDim.y + threadIdx.y; // 0..111
    const int cq = blockIdx.y;                            // 0..2
    const int b  = blockIdx.z;                            // 0..15

    const int bi = g_base[i];
    const int bj = g_base[j];

    const float m0 = 127.5f * c_M[cq][0];
    const float m1 = 127.5f * c_M[cq][1];
    const float m2 = 127.5f * c_M[cq][2];

    const float* xb = x + (size_t)b * 3 * NPLANE;

    // 3x3 YCbCr patch (zero-weight rows/cols are address-clamped, weight=0)
    float t[3][3];
    #pragma unroll
    for (int r = 0; r < 3; r++) {
        int row = bi + r; if (row > HW - 1) row = HW - 1;
        #pragma unroll
        for (int s = 0; s < 3; s++) {
            int col = bj + s; if (col > HW - 1) col = HW - 1;
            int off = row * HW + col;
            float p0 = __ldg(xb + off);
            float p1 = __ldg(xb + NPLANE + off);
            float p2 = __ldg(xb + 2 * NPLANE + off);
            t[r][s] = fmaf(m0, p0, fmaf(m1, p1, m2 * p2));
        }
    }

    // Row contraction: gv[u][s] = sum_r W[i][u][r] * t[r][s]
    float gv[8][3];
    #pragma unroll
    for (int u = 0; u < 8; u++) {
        float w0 = g_W[i][u][0];
        float w1 = g_W[i][u][1];
        float w2 = g_W[i][u][2];
        #pragma unroll
        for (int s = 0; s < 3; s++)
            gv[u][s] = fmaf(w0, t[0][s], fmaf(w1, t[1][s], w2 * t[2][s]));
    }

    // Column weights for this j
    float wh[8][3];
    #pragma unroll
    for (int v = 0; v < 8; v++) {
        wh[v][0] = g_W[j][v][0];
        wh[v][1] = g_W[j][v][1];
        wh[v][2] = g_W[j][v][2];
    }

    float* outp = out + ((size_t)(b * 162 + cq * 54)) * NPLANE + i * HW + j;

    int m = 0;
    #pragma unroll
    for (int idx = 0; idx < 64; idx++) {
        if ((SUB_MASK >> idx) & 1ULL) continue;   // dropped SUB channel
        const int u = idx >> 3;
        const int v = idx & 7;
        float val = fmaf(gv[u][0], wh[v][0],
                    fmaf(gv[u][1], wh[v][1],
                         gv[u][2] * wh[v][2]));
        outp[(size_t)m * NPLANE] = val;
        m++;
    }
}

// ---------------------------------------------------------------------------
extern "C" void kernel_launch(void* const* d_in, const int* in_sizes, int n_in,
                              void* d_out, int out_size) {
    const float* x = (const float*)d_in[0];   // (16, 3, 112, 112) fp32
    float* out = (float*)d_out;               // (16, 162, 112, 112) fp32

    init_weights_kernel<<<1, 128>>>();

    dim3 block(HW, 4);            // 448 threads: j x 4 rows of i
    dim3 grid(HW / 4, 3, NBATCH); // (28, 3, 16)
    dct_main_kernel<<<grid, block>>>(x, out);
}

// round 4
// speedup vs baseline: 1.0476x; 1.0476x over previous
#include <cuda_runtime.h>
#include <math.h>

// ---------------------------------------------------------------------------
// DCTModel: fused upsample(112->896) + RGB->YCbCr + 8x8 DCT + 54-channel select,
// algebraically collapsed: each 8x8 block depends on a 3x3 input patch; all
// additive constants land only in the (dropped) DC coefficient.
//
//   out[b, cq*54+m(u,v), i, 2x+jj]
//     = sum_{r,s} W[i][u][r] * W[j][v][s] * t[b,cq, bi+r, bj+s]
//   t = 127.5 * (RGB2YCBCR @ x)
//
// R3 changes vs R2 (L1tex was the 57.9% binder):
//  - YCbCr tile staged in smem per block (12 LDS replace 81 scattered LDG)
//  - W table in smem with padded stride 25 (conflict-free scalar LDS)
//  - 2-wide j per thread -> STG.64 stores (27 instead of 54 STG.32)
// ---------------------------------------------------------------------------

#define HW 112
#define NPLANE 12544
#define NBATCH 16

#define BX 56           // j-pairs per block (covers all 112 j)
#define BY 4            // i rows per block
#define NTHREADS (BX*BY)
#define ROWS_T 6        // input rows needed by a 4-row i-group (<= 3+2+pad)
#define COLS_T 114      // 112 + 2 pad cols (zero-weight overhang)
#define WSTRIDE 25      // padded row stride for W table (odd -> no bank conflicts)

__device__ float g_W[HW][8][3];   // fused (DCT x upsample) weights, rows==cols
__device__ int   g_base[HW];      // base input index per block index

__constant__ float c_M[3][3] = {
    { 0.299f,     0.587f,    0.114f    },
    {-0.168736f, -0.331264f, 0.5f      },
    { 0.5f,      -0.418688f, -0.081312f}
};

// SUB_CHANNELS = {0,1,2,3,4,5,8,9,16,24}
#define SUB_MASK 0x000000000101033FULL

// ---------------------------------------------------------------------------
// Init: build W in fp64, mirroring numpy's float64 src/floor/clamp exactly.
// ---------------------------------------------------------------------------
__global__ void init_weights_kernel() {
    int i = threadIdx.x;
    if (i >= HW) return;

    int    i0[8];
    double w[8];
    int base = 1 << 30;
    #pragma unroll
    for (int x = 0; x < 8; x++) {
        int o = 8 * i + x;
        double src = ((double)o * 111.0) / 895.0;
        int f = (int)floor(src);
        if (f > HW - 2) f = HW - 2;
        i0[x] = f;
        w[x]  = src - (double)f;
        if (f < base) base = f;
    }
    g_base[i] = base;

    double a[8][3];
    #pragma unroll
    for (int x = 0; x < 8; x++) { a[x][0] = a[x][1] = a[x][2] = 0.0; }
    #pragma unroll
    for (int x = 0; x < 8; x++) {
        int off = i0[x] - base;           // 0 or 1
        a[x][off]     += 1.0 - w[x];
        a[x][off + 1] += w[x];
    }

    const double PI = 3.14159265358979323846;
    #pragma unroll
    for (int u = 0; u < 8; u++) {
        double alpha = (u == 0) ? (1.0 / sqrt(2.0)) : 1.0;
        #pragma unroll
        for (int r = 0; r < 3; r++) {
            double s = 0.0;
            #pragma unroll
            for (int x = 0; x < 8; x++)
                s += cos(((2 * x + 1) * u) * PI / 16.0) * a[x][r];
            g_W[i][u][r] = (float)(s * alpha * 0.5);   // alpha_u / 2
        }
    }
}

// ---------------------------------------------------------------------------
// Main: block = (56 j-pairs, 4 i-rows), grid = (28 i-groups, 3 cq, 16 b).
// ---------------------------------------------------------------------------
__global__ __launch_bounds__(NTHREADS)
void dct_main_kernel(const float* __restrict__ x, float* __restrict__ out) {
    __shared__ float sW[HW * WSTRIDE];        // 11.2 KB
    __shared__ float sT[ROWS_T * COLS_T];     // 2.7 KB  (YCbCr tile)
    __shared__ int   sB[HW];

    const int tx = threadIdx.x;               // 0..55 (j-pair)
    const int ty = threadIdx.y;               // 0..3  (i within group)
    const int tid = ty * BX + tx;
    const int cq = blockIdx.y;
    const int b  = blockIdx.z;
    const int i0 = blockIdx.x * BY;

    const int rmin = __ldg(&g_base[i0]);      // base row of this i-group

    // ---- cooperative smem fill -------------------------------------------
    const float* gw = &g_W[0][0][0];
    for (int e = tid; e < HW * 24; e += NTHREADS) {
        int j = e / 24, r = e - j * 24;
        sW[j * WSTRIDE + r] = gw[e];
    }
    if (tid < HW) sB[tid] = g_base[tid];

    {
        const float m0 = 127.5f * c_M[cq][0];
        const float m1 = 127.5f * c_M[cq][1];
        const float m2 = 127.5f * c_M[cq][2];
        const float* xb = x + (size_t)b * 3 * NPLANE;
        for (int e = tid; e < ROWS_T * COLS_T; e += NTHREADS) {
            int lr = e / COLS_T, c = e - lr * COLS_T;
            int srow = rmin + lr; if (srow > HW - 1) srow = HW - 1;
            int scol = c;         if (scol > HW - 1) scol = HW - 1;
            int off = srow * HW + scol;
            float p0 = __ldg(xb + off);
            float p1 = __ldg(xb + NPLANE + off);
            float p2 = __ldg(xb + 2 * NPLANE + off);
            sT[e] = fmaf(m0, p0, fmaf(m1, p1, m2 * p2));
        }
    }
    __syncthreads();

    // ---- per-thread work --------------------------------------------------
    const int i  = i0 + ty;
    const int j0 = 2 * tx;
    const int bi = sB[i];
    const int bj0 = sB[j0];
    const int off1 = sB[j0 + 1] - bj0;        // 0 or 1
    const int lr = bi - rmin;                  // 0..3

    // 3x4 YCbCr patch from smem (covers both j's windows)
    float t[3][4];
    #pragma unroll
    for (int r = 0; r < 3; r++) {
        const float* row = &sT[(lr + r) * COLS_T + bj0];
        #pragma unroll
        for (int s = 0; s < 4; s++) t[r][s] = row[s];
    }

    // Row contraction: gv[u][s] = sum_r W[i][u][r] * t[r][s]
    float gv[8][4];
    {
        const float* wr = &sW[i * WSTRIDE];
        #pragma unroll
        for (int u = 0; u < 8; u++) {
            float w0 = wr[u * 3 + 0], w1 = wr[u * 3 + 1], w2 = wr[u * 3 + 2];
            #pragma unroll
            for (int s = 0; s < 4; s++)
                gv[u][s] = fmaf(w0, t[0][s], fmaf(w1, t[1][s], w2 * t[2][s]));
        }
    }

    // Shifted copy for the second j (off1 resolved once, compile-time indexing)
    float gb[8][3];
    const bool sh = (off1 != 0);
    #pragma unroll
    for (int u = 0; u < 8; u++) {
        #pragma unroll
        for (int k = 0; k < 3; k++)
            gb[u][k] = sh ? gv[u][k + 1] : gv[u][k];
    }

    // Epilogue: 54 coefficients, float2 stores across the j-pair
    float* outp = out + ((size_t)(b * 162 + cq * 54)) * NPLANE + i * HW + j0;
    const float* wA = &sW[j0 * WSTRIDE];
    const float* wB = &sW[(j0 + 1) * WSTRIDE];

    #pragma unroll
    for (int v = 0; v < 8; v++) {
        float a0 = wA[v * 3 + 0], a1 = wA[v * 3 + 1], a2 = wA[v * 3 + 2];
        float b0 = wB[v * 3 + 0], b1 = wB[v * 3 + 1], b2 = wB[v * 3 + 2];
        #pragma unroll
        for (int u = 0; u < 8; u++) {
            const int idx = u * 8 + v;
            if ((SUB_MASK >> idx) & 1ULL) continue;           // dropped channel
            const int m = idx - __popcll(SUB_MASK & ((1ULL << idx) - 1ULL));
            float2 val;
            val.x = fmaf(gv[u][0], a0, fmaf(gv[u][1], a1, gv[u][2] * a2));
            val.y = fmaf(gb[u][0], b0, fmaf(gb[u][1], b1, gb[u][2] * b2));
            *reinterpret_cast<float2*>(outp + (size_t)m * NPLANE) = val;
        }
    }
}

// ---------------------------------------------------------------------------
extern "C" void kernel_launch(void* const* d_in, const int* in_sizes, int n_in,
                              void* d_out, int out_size) {
    const float* x = (const float*)d_in[0];   // (16, 3, 112, 112) fp32
    float* out = (float*)d_out;               // (16, 162, 112, 112) fp32

    init_weights_kernel<<<1, 128>>>();

    dim3 block(BX, BY);                       // 224 threads
    dim3 grid(HW / BY, 3, NBATCH);            // (28, 3, 16)
    dct_main_kernel<<<grid, block>>>(x, out);
}